// round 11
// baseline (speedup 1.0000x reference)
#include <cuda_runtime.h>
#include <cstdint>
#include <cfloat>

#define NS 16384
#define NQ 16384
#define DIM 64
#define NC 64
#define QT 64
#define ST 128
#define NCHUNK (NS / ST)          // 128
#define ROWF 68                   // padded row: 64 data + 4 pad floats (272 B)
#define DELTA 1e-3f

// ---------------- device scratch ----------------
__device__ __align__(16) float g_sq_s[NS];
__device__ __align__(16) float g_sq_q[NQ];
__device__ int g_lab[NS];
__device__ int g_flag_count;
__device__ int g_flag_q[NQ];

// ---------------- helpers ----------------
__device__ __forceinline__ uint32_t smem_u32(const void* p) {
    uint32_t a;
    asm("{ .reg .u64 t; cvta.to.shared.u64 t, %1; cvt.u32.u64 %0, t; }" : "=r"(a) : "l"(p));
    return a;
}
__device__ __forceinline__ unsigned long long fma2(unsigned long long a,
                                                   unsigned long long b,
                                                   unsigned long long c) {
    unsigned long long d;
    asm("fma.rn.f32x2 %0, %1, %2, %3;" : "=l"(d) : "l"(a), "l"(b), "l"(c));
    return d;
}
#define CP_ASYNC16(dst, src) \
    asm volatile("cp.async.cg.shared.global [%0], [%1], 16;" :: "r"(dst), "l"(src))
#define CP_COMMIT() asm volatile("cp.async.commit_group;" ::: "memory")
#define CP_WAIT1()  asm volatile("cp.async.wait_group 1;" ::: "memory")

// ---------------- prep: norms + labels (4 threads per row) ----------------
__global__ __launch_bounds__(256) void prep_kernel(const float* __restrict__ S,
                                                   const float* __restrict__ Q,
                                                   const float* __restrict__ OH) {
    int gid = blockIdx.x * blockDim.x + threadIdx.x;   // 65536 threads
    if (gid == 0) g_flag_count = 0;
    int row = gid >> 2;
    int seg = gid & 3;
    int kb  = seg * 16;

    float ps = 0.f, pq = 0.f;
    #pragma unroll
    for (int i = 0; i < 4; i++) {
        float4 sv = *(const float4*)(S + (size_t)row * DIM + kb + i * 4);
        float4 qv = *(const float4*)(Q + (size_t)row * DIM + kb + i * 4);
        ps += sv.x * sv.x + sv.y * sv.y + sv.z * sv.z + sv.w * sv.w;
        pq += qv.x * qv.x + qv.y * qv.y + qv.z * qv.z + qv.w * qv.w;
    }
    #pragma unroll
    for (int off = 1; off <= 2; off <<= 1) {
        ps += __shfl_xor_sync(0xffffffffu, ps, off);
        pq += __shfl_xor_sync(0xffffffffu, pq, off);
    }
    float best = -1.f;
    int bi = kb;
    const float4* oh = (const float4*)(OH + (size_t)row * NC + kb);
    #pragma unroll
    for (int i = 0; i < 4; i++) {
        float4 v = oh[i];
        float vv[4] = {v.x, v.y, v.z, v.w};
        #pragma unroll
        for (int j = 0; j < 4; j++)
            if (vv[j] > best) { best = vv[j]; bi = kb + i * 4 + j; }
    }
    #pragma unroll
    for (int off = 1; off <= 2; off <<= 1) {
        float ob = __shfl_xor_sync(0xffffffffu, best, off);
        int   oi = __shfl_xor_sync(0xffffffffu, bi, off);
        if (ob > best || (ob == best && oi < bi)) { best = ob; bi = oi; }
    }
    if (seg == 0) { g_sq_s[row] = ps; g_sq_q[row] = pq; g_lab[row] = bi; }
}

// ---------------- main fp32 FFMA2 kernel ----------------
// smem bytes: Q 64*272=17408 | S 2*128*272=69632 | sqs 2*512 | stash 3*256 | lab 256
#define OFF_Q   0
#define OFF_S   17408
#define OFF_SQ  (OFF_S + 2 * ST * ROWF * 4)        // 87040
#define OFF_RD  (OFF_SQ + 2 * 512)                 // 88064 (d1)
#define OFF_RE  (OFF_RD + 256)                     // (d2)
#define OFF_RX  (OFF_RE + 256)                     // (idx)
#define OFF_LAB (OFF_RX + 256)
#define SMEM_SZ (OFF_LAB + 256)

__device__ __forceinline__ void issueS(uint32_t sbase, const char* Sg, int t, int buf, int tid) {
    // 128 rows x 256 B -> padded rows of 272 B; 2048 x 16B chunks, 8 per thread
    const char* src = Sg + (size_t)t * ST * 256;
    uint32_t dst = sbase + OFF_S + (uint32_t)buf * (ST * ROWF * 4);
    #pragma unroll
    for (int j = 0; j < 8; j++) {
        int e = tid + j * 256;
        int row = e >> 4;
        int c = e & 15;
        CP_ASYNC16(dst + (uint32_t)row * (ROWF * 4) + (uint32_t)c * 16, src + (size_t)e * 16);
    }
    if (tid < 32) {
        const char* sq = (const char*)g_sq_s + (size_t)t * ST * 4;
        CP_ASYNC16(sbase + OFF_SQ + (uint32_t)buf * 512 + (uint32_t)tid * 16, sq + tid * 16);
    }
}

__global__ __launch_bounds__(256, 2) void knn_kernel(const float* __restrict__ S,
                                                     const float* __restrict__ Q,
                                                     float* __restrict__ out) {
    extern __shared__ __align__(16) char smem[];
    const uint32_t sbase = smem_u32(smem);
    const int tid  = threadIdx.x;
    const int lane = tid & 31;            // support group: s = lane + 32p
    const int wrp  = tid >> 5;            // query group: q = wrp*8 + i
    const int qbase = blockIdx.x * QT;
    float* qsm = (float*)(smem + OFF_Q);

    // -- Q tile: 64 rows x 64 floats into padded rows (natural layout) --
    #pragma unroll
    for (int j = 0; j < 4; j++) {
        int g = tid + j * 256;
        int r = g >> 4;
        int c = g & 15;
        float4 v = *(const float4*)(Q + (size_t)(qbase + r) * DIM + c * 4);
        *(float4*)(qsm + r * ROWF + c * 4) = v;
    }
    // -- prologue: chunks 0,1 --
    issueS(sbase, (const char*)S, 0, 0, tid);
    CP_COMMIT();
    issueS(sbase, (const char*)S, 1, 1, tid);
    CP_COMMIT();
    __syncthreads();   // Q tile visible

    float m1[8], m2[8];
    int   i1[8];
    #pragma unroll
    for (int i = 0; i < 8; i++) { m1[i] = FLT_MAX; m2[i] = FLT_MAX; i1[i] = 0; }

    const float* qrow = qsm + wrp * 8 * ROWF;

    for (int t = 0; t < NCHUNK; t++) {
        const int buf = t & 1;
        CP_WAIT1();
        __syncthreads();

        const float* sb = (const float*)(smem + OFF_S + buf * (ST * ROWF * 4));

        unsigned long long acc[8][4];
        #pragma unroll
        for (int i = 0; i < 8; i++)
            #pragma unroll
            for (int p = 0; p < 4; p++) acc[i][p] = 0ull;

        #pragma unroll
        for (int k0 = 0; k0 < DIM; k0 += 4) {
            ulonglong2 su[4];
            #pragma unroll
            for (int p = 0; p < 4; p++)
                su[p] = *(const ulonglong2*)(sb + (lane + 32 * p) * ROWF + k0);
            #pragma unroll
            for (int i = 0; i < 8; i++) {
                ulonglong2 qu = *(const ulonglong2*)(qrow + i * ROWF + k0);
                #pragma unroll
                for (int p = 0; p < 4; p++) {
                    acc[i][p] = fma2(qu.x, su[p].x, acc[i][p]);
                    acc[i][p] = fma2(qu.y, su[p].y, acc[i][p]);
                }
            }
        }

        // epilogue: cross = even+odd partials; d2' = ||s||^2 - 2*cross; top-2
        const float* sq = (const float*)(smem + OFF_SQ + buf * 512);
        float sqv[4];
        #pragma unroll
        for (int p = 0; p < 4; p++) sqv[p] = sq[lane + 32 * p];
        const int sb0 = t * ST + lane;
        #pragma unroll
        for (int p = 0; p < 4; p++) {
            const int idx = sb0 + 32 * p;
            #pragma unroll
            for (int i = 0; i < 8; i++) {
                float lo = __uint_as_float((unsigned)(acc[i][p] & 0xffffffffull));
                float hi = __uint_as_float((unsigned)(acc[i][p] >> 32));
                float d = fmaf(-2.f, lo + hi, sqv[p]);
                if (d < m1[i])      { m2[i] = m1[i]; m1[i] = d; i1[i] = idx; }
                else if (d < m2[i]) { m2[i] = d; }
            }
        }

        __syncthreads();
        if (t + 2 < NCHUNK) issueS(sbase, (const char*)S, t + 2, buf, tid);
        CP_COMMIT();
    }

    // -- warp-level reduce: each warp fully owns its 8 queries --
    float* rd = (float*)(smem + OFF_RD);
    float* re = (float*)(smem + OFF_RE);
    int*   rx = (int*)(smem + OFF_RX);
    int*   lab = (int*)(smem + OFF_LAB);
    #pragma unroll
    for (int i = 0; i < 8; i++) {
        float d = m1[i], e = m2[i];
        int   x = i1[i];
        #pragma unroll
        for (int off = 16; off > 0; off >>= 1) {
            float od = __shfl_down_sync(0xffffffffu, d, off);
            float oe = __shfl_down_sync(0xffffffffu, e, off);
            int   ox = __shfl_down_sync(0xffffffffu, x, off);
            if (od < d || (od == d && ox < x)) { e = fminf(d, oe); d = od; x = ox; }
            else                               { e = fminf(e, od); }
        }
        if (lane == 0) { rd[wrp * 8 + i] = d; re[wrp * 8 + i] = e; rx[wrp * 8 + i] = x; }
    }
    __syncthreads();

    if (tid < QT) {
        if (re[tid] - rd[tid] < DELTA) {
            int slot = atomicAdd(&g_flag_count, 1);
            g_flag_q[slot] = qbase + tid;
        }
        lab[tid] = g_lab[rx[tid]];
    }
    __syncthreads();

    // -- one-hot write: 64 rows x 64 cols = 1024 float4, 4 per thread --
    #pragma unroll
    for (int j = 0; j < 4; j++) {
        int g = tid + j * 256;
        int row = g >> 4;
        int c4 = (g & 15) * 4;
        int lb = lab[row];
        float4 v;
        v.x = (c4 + 0 == lb) ? 1.f : 0.f;
        v.y = (c4 + 1 == lb) ? 1.f : 0.f;
        v.z = (c4 + 2 == lb) ? 1.f : 0.f;
        v.w = (c4 + 3 == lb) ? 1.f : 0.f;
        *(float4*)(out + (size_t)(qbase + row) * NC + c4) = v;
    }
}

// ---------------- exact cleanup for flagged queries ----------------
__global__ __launch_bounds__(256) void cleanup_kernel(const float* __restrict__ S,
                                                      const float* __restrict__ Q,
                                                      float* __restrict__ out) {
    __shared__ float qrow[DIM];
    __shared__ float bd[256];
    __shared__ int   bix[256];
    const int tid = threadIdx.x;
    const int nflag = g_flag_count;
    for (int f = blockIdx.x; f < nflag; f += gridDim.x) {
        int q = g_flag_q[f];
        if (tid < DIM) qrow[tid] = Q[(size_t)q * DIM + tid];
        __syncthreads();
        float sqq = g_sq_q[q];
        float best = FLT_MAX;
        int bidx = 0;
        for (int s = tid; s < NS; s += 256) {
            const float* sr = S + (size_t)s * DIM;
            float acc = 0.f;
            #pragma unroll
            for (int k = 0; k < DIM; k++) acc = fmaf(qrow[k], sr[k], acc);
            float d2 = fmaf(-2.f, acc, sqq + g_sq_s[s]);
            if (d2 < best) { best = d2; bidx = s; }
        }
        bd[tid] = best; bix[tid] = bidx;
        __syncthreads();
        for (int off = 128; off > 0; off >>= 1) {
            if (tid < off) {
                float od = bd[tid + off]; int oi = bix[tid + off];
                if (od < bd[tid] || (od == bd[tid] && oi < bix[tid])) {
                    bd[tid] = od; bix[tid] = oi;
                }
            }
            __syncthreads();
        }
        int lb = g_lab[bix[0]];
        if (tid < NC) out[(size_t)q * NC + tid] = (tid == lb) ? 1.f : 0.f;
        __syncthreads();
    }
}

// ---------------- launch ----------------
extern "C" void kernel_launch(void* const* d_in, const int* in_sizes, int n_in,
                              void* d_out, int out_size) {
    const float* S  = (const float*)d_in[0];
    const float* Q  = (const float*)d_in[1];
    const float* OH = (const float*)d_in[2];
    float* out = (float*)d_out;

    static bool attr_set = false;
    if (!attr_set) {
        cudaFuncSetAttribute(knn_kernel,
                             cudaFuncAttributeMaxDynamicSharedMemorySize, SMEM_SZ);
        attr_set = true;
    }

    prep_kernel<<<NS / 64, 256>>>(S, Q, OH);
    knn_kernel<<<NQ / QT, 256, SMEM_SZ>>>(S, Q, out);
    cleanup_kernel<<<128, 256>>>(S, Q, out);
}